// round 1
// baseline (speedup 1.0000x reference)
#include <cuda_runtime.h>
#include <math.h>
#include <stdint.h>

#define MROWS 8192           // B*T = 4*2048
#define CDIM  768
#define TSEQ  2048
#define NBATCH 4
#define NHEAD 12
#define HD    64

// ---------------- scratch (no allocations allowed) ----------------
__device__ float g_ln [(size_t)MROWS * CDIM];
__device__ float g_qkv[(size_t)MROWS * 3 * CDIM];
__device__ float g_att[(size_t)MROWS * CDIM];
__device__ float g_x1 [(size_t)MROWS * CDIM];
__device__ float g_fc [(size_t)MROWS * 4 * CDIM];

// ---------------- helpers ----------------
__device__ __forceinline__ float warp_sum(float v) {
#pragma unroll
    for (int m = 16; m; m >>= 1) v += __shfl_xor_sync(0xffffffffu, v, m);
    return v;
}

__device__ __forceinline__ float gelu_tanh(float x) {
    const float c = 0.7978845608028654f;  // sqrt(2/pi)
    float x3 = x * x * x;
    return 0.5f * x * (1.0f + tanhf(c * (x + 0.044715f * x3)));
}

// ---------------- LayerNorm (row = 768, ddof=1) ----------------
__global__ __launch_bounds__(256) void ln_kernel(
    const float* __restrict__ x, const float* __restrict__ w,
    const float* __restrict__ b, float* __restrict__ y)
{
    const int row = blockIdx.x;
    const float* xr = x + (size_t)row * CDIM;
    float* yr = y + (size_t)row * CDIM;
    const int t = threadIdx.x;

    float v0 = xr[t], v1 = xr[t + 256], v2 = xr[t + 512];
    float s  = v0 + v1 + v2;
    float s2 = v0 * v0 + v1 * v1 + v2 * v2;

    __shared__ float sh[2][8];
    s = warp_sum(s); s2 = warp_sum(s2);
    int wid = t >> 5, lane = t & 31;
    if (lane == 0) { sh[0][wid] = s; sh[1][wid] = s2; }
    __syncthreads();
    if (wid == 0) {
        float a = (lane < 8) ? sh[0][lane] : 0.0f;
        float c = (lane < 8) ? sh[1][lane] : 0.0f;
        a = warp_sum(a); c = warp_sum(c);
        if (lane == 0) { sh[0][0] = a; sh[1][0] = c; }
    }
    __syncthreads();
    s = sh[0][0]; s2 = sh[1][0];

    float mean = s * (1.0f / (float)CDIM);
    float var  = (s2 - (float)CDIM * mean * mean) * (1.0f / (float)(CDIM - 1));
    float rstd = rsqrtf(var + 1e-5f);

    yr[t]       = (v0 - mean) * rstd * w[t]       + b[t];
    yr[t + 256] = (v1 - mean) * rstd * w[t + 256] + b[t + 256];
    yr[t + 512] = (v2 - mean) * rstd * w[t + 512] + b[t + 512];
}

// ---------------- SGEMM 128x128x8, 8x8 microtile, templated epilogue ----
// EPI: 0 = +bias, 1 = gelu(+bias), 2 = +bias + residual
template<int EPI>
__global__ __launch_bounds__(256) void sgemm128(
    int M, int N, int K,
    const float* __restrict__ A, const float* __restrict__ B,
    const float* __restrict__ bias, const float* __restrict__ Res,
    float* __restrict__ C)
{
    __shared__ float As[8][128];
    __shared__ float Bs[8][128];

    const int tid = threadIdx.x;
    const int tr  = tid >> 4;        // 0..15
    const int tc  = tid & 15;        // 0..15
    const int aRow = tid >> 1;       // 0..127
    const int aCol = (tid & 1) * 4;  // 0 or 4
    const int bRow = tid >> 5;       // 0..7
    const int bCol = (tid & 31) * 4; // 0..124

    const float* Ab = A + (size_t)blockIdx.y * 128 * K;
    const float* Bb = B + (size_t)blockIdx.x * 128;

    float acc[8][8];
#pragma unroll
    for (int i = 0; i < 8; i++)
#pragma unroll
        for (int j = 0; j < 8; j++) acc[i][j] = 0.0f;

    for (int k0 = 0; k0 < K; k0 += 8) {
        float4 av = *(const float4*)(Ab + (size_t)aRow * K + k0 + aCol);
        As[aCol + 0][aRow] = av.x;
        As[aCol + 1][aRow] = av.y;
        As[aCol + 2][aRow] = av.z;
        As[aCol + 3][aRow] = av.w;
        *(float4*)&Bs[bRow][bCol] =
            *(const float4*)(Bb + (size_t)(k0 + bRow) * N + bCol);
        __syncthreads();
#pragma unroll
        for (int k = 0; k < 8; k++) {
            float4 a0 = *(const float4*)&As[k][tr * 8];
            float4 a1 = *(const float4*)&As[k][tr * 8 + 4];
            float4 b0 = *(const float4*)&Bs[k][tc * 8];
            float4 b1 = *(const float4*)&Bs[k][tc * 8 + 4];
            float ra[8] = {a0.x, a0.y, a0.z, a0.w, a1.x, a1.y, a1.z, a1.w};
            float rb[8] = {b0.x, b0.y, b0.z, b0.w, b1.x, b1.y, b1.z, b1.w};
#pragma unroll
            for (int i = 0; i < 8; i++)
#pragma unroll
                for (int j = 0; j < 8; j++)
                    acc[i][j] = fmaf(ra[i], rb[j], acc[i][j]);
        }
        __syncthreads();
    }

    const int row0 = blockIdx.y * 128 + tr * 8;
    const int col0 = blockIdx.x * 128 + tc * 8;
#pragma unroll
    for (int i = 0; i < 8; i++) {
        size_t off = (size_t)(row0 + i) * N + col0;
#pragma unroll
        for (int j0 = 0; j0 < 8; j0 += 4) {
            float t0 = acc[i][j0 + 0] + bias[col0 + j0 + 0];
            float t1 = acc[i][j0 + 1] + bias[col0 + j0 + 1];
            float t2 = acc[i][j0 + 2] + bias[col0 + j0 + 2];
            float t3 = acc[i][j0 + 3] + bias[col0 + j0 + 3];
            if (EPI == 1) {
                t0 = gelu_tanh(t0); t1 = gelu_tanh(t1);
                t2 = gelu_tanh(t2); t3 = gelu_tanh(t3);
            }
            if (EPI == 2) {
                t0 += Res[off + j0 + 0];
                t1 += Res[off + j0 + 1];
                t2 += Res[off + j0 + 2];
                t3 += Res[off + j0 + 3];
            }
            float4 v; v.x = t0; v.y = t1; v.z = t2; v.w = t3;
            *(float4*)(C + off + j0) = v;
        }
    }
}

// ---------------- Flash attention, fp32, causal, Br=Bc=64, D=64 ----------
// qkv layout: [B*T, 3C]; q at col h*64, k at C + h*64, v at 2C + h*64.
// Block: 256 threads as 16x16 grid; each thread owns a 4x4 tile of S / O.
#define FA_SMEM ((3 * 64 * 65 + 64 * 64) * 4)

__global__ __launch_bounds__(256) void flash_attn_kernel(
    const float* __restrict__ qkv, float* __restrict__ out)
{
    extern __shared__ float sm[];
    float* Qt = sm;               // [64][65], Qt[d][row]
    float* Kt = Qt + 64 * 65;     // [64][65], Kt[d][col]
    float* Pt = Kt + 64 * 65;     // [64][65], Pt[col][row]
    float* Vs = Pt + 64 * 65;     // [64][64], Vs[row][dim]

    const int tid = threadIdx.x;
    const int tr = tid >> 4;      // 0..15  -> rows tr*4..tr*4+3
    const int tc = tid & 15;      // 0..15  -> cols tc*4..tc*4+3
    const int b = blockIdx.z, h = blockIdx.y, qt = blockIdx.x;
    const int q0 = qt * 64;
    const size_t rs = 3 * CDIM;
    const float* qb = qkv + (size_t)b * TSEQ * rs + h * HD;
    const float* kb = qb + CDIM;
    const float* vb = qb + 2 * CDIM;

    // load Q tile transposed
#pragma unroll
    for (int it = 0; it < 4; it++) {
        int e = (tid + it * 256) * 4;
        int r = e >> 6, d = e & 63;
        float4 v = *(const float4*)(qb + (size_t)(q0 + r) * rs + d);
        Qt[(d + 0) * 65 + r] = v.x;
        Qt[(d + 1) * 65 + r] = v.y;
        Qt[(d + 2) * 65 + r] = v.z;
        Qt[(d + 3) * 65 + r] = v.w;
    }

    float o[4][4];
#pragma unroll
    for (int i = 0; i < 4; i++)
#pragma unroll
        for (int c = 0; c < 4; c++) o[i][c] = 0.0f;
    float mr[4], lr[4];
#pragma unroll
    for (int i = 0; i < 4; i++) { mr[i] = -1e30f; lr[i] = 0.0f; }

    for (int kt = 0; kt <= qt; kt++) {
        const int k0 = kt * 64;
        __syncthreads();   // protect Kt/Vs/Pt reuse (and Q visibility on iter 0)
#pragma unroll
        for (int it = 0; it < 4; it++) {
            int e = (tid + it * 256) * 4;
            int r = e >> 6, d = e & 63;
            float4 kv = *(const float4*)(kb + (size_t)(k0 + r) * rs + d);
            Kt[(d + 0) * 65 + r] = kv.x;
            Kt[(d + 1) * 65 + r] = kv.y;
            Kt[(d + 2) * 65 + r] = kv.z;
            Kt[(d + 3) * 65 + r] = kv.w;
            float4 vv = *(const float4*)(vb + (size_t)(k0 + r) * rs + d);
            *(float4*)&Vs[r * 64 + d] = vv;
        }
        __syncthreads();

        // S = Q K^T for this thread's 4x4 tile
        float s[4][4];
#pragma unroll
        for (int i = 0; i < 4; i++)
#pragma unroll
            for (int j = 0; j < 4; j++) s[i][j] = 0.0f;
#pragma unroll 8
        for (int d = 0; d < 64; d++) {
            float ra[4], rb[4];
#pragma unroll
            for (int i = 0; i < 4; i++) ra[i] = Qt[d * 65 + tr * 4 + i];
#pragma unroll
            for (int j = 0; j < 4; j++) rb[j] = Kt[d * 65 + tc * 4 + j];
#pragma unroll
            for (int i = 0; i < 4; i++)
#pragma unroll
                for (int j = 0; j < 4; j++)
                    s[i][j] = fmaf(ra[i], rb[j], s[i][j]);
        }

        const float scale = 0.125f;   // 1/sqrt(64)
        const bool diag = (kt == qt);
#pragma unroll
        for (int i = 0; i < 4; i++)
#pragma unroll
            for (int j = 0; j < 4; j++) {
                s[i][j] *= scale;
                if (diag && (k0 + tc * 4 + j) > (q0 + tr * 4 + i))
                    s[i][j] = -1e30f;
            }

        // online softmax (reduce across the 16 lanes sharing a row)
#pragma unroll
        for (int i = 0; i < 4; i++) {
            float tm = fmaxf(fmaxf(s[i][0], s[i][1]), fmaxf(s[i][2], s[i][3]));
#pragma unroll
            for (int m = 8; m; m >>= 1)
                tm = fmaxf(tm, __shfl_xor_sync(0xffffffffu, tm, m));
            float mn = fmaxf(mr[i], tm);
            float alpha = expf(mr[i] - mn);
            float psum = 0.0f;
#pragma unroll
            for (int j = 0; j < 4; j++) {
                s[i][j] = expf(s[i][j] - mn);
                psum += s[i][j];
            }
#pragma unroll
            for (int m = 8; m; m >>= 1)
                psum += __shfl_xor_sync(0xffffffffu, psum, m);
            lr[i] = lr[i] * alpha + psum;
            mr[i] = mn;
#pragma unroll
            for (int c = 0; c < 4; c++) o[i][c] *= alpha;
        }

        // store P transposed for the PV gemm
#pragma unroll
        for (int i = 0; i < 4; i++)
#pragma unroll
            for (int j = 0; j < 4; j++)
                Pt[(tc * 4 + j) * 65 + tr * 4 + i] = s[i][j];
        __syncthreads();

        // O += P V
#pragma unroll 8
        for (int j = 0; j < 64; j++) {
            float ra[4], rb[4];
#pragma unroll
            for (int i = 0; i < 4; i++) ra[i] = Pt[j * 65 + tr * 4 + i];
#pragma unroll
            for (int c = 0; c < 4; c++) rb[c] = Vs[j * 64 + tc * 4 + c];
#pragma unroll
            for (int i = 0; i < 4; i++)
#pragma unroll
                for (int c = 0; c < 4; c++)
                    o[i][c] = fmaf(ra[i], rb[c], o[i][c]);
        }
    }

    // normalize and write: out[(b*T + q) * C + h*64 + d]
#pragma unroll
    for (int i = 0; i < 4; i++) {
        float inv = 1.0f / lr[i];
        float4 v;
        v.x = o[i][0] * inv; v.y = o[i][1] * inv;
        v.z = o[i][2] * inv; v.w = o[i][3] * inv;
        *(float4*)(out + (size_t)(b * TSEQ + q0 + tr * 4 + i) * CDIM
                       + h * HD + tc * 4) = v;
    }
}

// ---------------- launch ----------------
extern "C" void kernel_launch(void* const* d_in, const int* in_sizes, int n_in,
                              void* d_out, int out_size)
{
    const float* x       = (const float*)d_in[0];
    const float* ln1_w   = (const float*)d_in[1];
    const float* ln1_b   = (const float*)d_in[2];
    const float* attn_w  = (const float*)d_in[3];
    const float* attn_b  = (const float*)d_in[4];
    const float* proj_w  = (const float*)d_in[5];
    const float* proj_b  = (const float*)d_in[6];
    const float* ln2_w   = (const float*)d_in[7];
    const float* ln2_b   = (const float*)d_in[8];
    const float* fc_w    = (const float*)d_in[9];
    const float* fc_b    = (const float*)d_in[10];
    const float* mproj_w = (const float*)d_in[11];
    const float* mproj_b = (const float*)d_in[12];
    float* out = (float*)d_out;

    float *ln, *qkv, *att, *x1, *fc;
    cudaGetSymbolAddress((void**)&ln,  g_ln);
    cudaGetSymbolAddress((void**)&qkv, g_qkv);
    cudaGetSymbolAddress((void**)&att, g_att);
    cudaGetSymbolAddress((void**)&x1,  g_x1);
    cudaGetSymbolAddress((void**)&fc,  g_fc);

    cudaFuncSetAttribute(flash_attn_kernel,
                         cudaFuncAttributeMaxDynamicSharedMemorySize, FA_SMEM);

    // 1) ln1
    ln_kernel<<<MROWS, 256>>>(x, ln1_w, ln1_b, ln);
    // 2) qkv = ln1 @ W_attn + b   [8192, 2304]
    sgemm128<0><<<dim3(2304 / 128, MROWS / 128), 256>>>(
        MROWS, 2304, CDIM, ln, attn_w, attn_b, nullptr, qkv);
    // 3) attention
    flash_attn_kernel<<<dim3(TSEQ / 64, NHEAD, NBATCH), 256, FA_SMEM>>>(qkv, att);
    // 4) x1 = x + att @ W_proj + b
    sgemm128<2><<<dim3(CDIM / 128, MROWS / 128), 256>>>(
        MROWS, CDIM, CDIM, att, proj_w, proj_b, x, x1);
    // 5) ln2
    ln_kernel<<<MROWS, 256>>>(x1, ln2_w, ln2_b, ln);
    // 6) fc = gelu(ln2 @ W_fc + b)   [8192, 3072]
    sgemm128<1><<<dim3(3072 / 128, MROWS / 128), 256>>>(
        MROWS, 3072, CDIM, ln, fc_w, fc_b, nullptr, fc);
    // 7) out = x1 + fc @ W_mproj + b
    sgemm128<2><<<dim3(CDIM / 128, MROWS / 128), 256>>>(
        MROWS, CDIM, 4 * CDIM, fc, mproj_w, mproj_b, x1, out);
}

// round 2
// speedup vs baseline: 1.8388x; 1.8388x over previous
#include <cuda_runtime.h>
#include <cuda_bf16.h>
#include <math.h>
#include <stdint.h>

#define MROWS 8192           // B*T = 4*2048
#define CDIM  768
#define TSEQ  2048
#define NBATCH 4
#define NHEAD 12
#define HD    64

// ---------------- scratch (no allocations allowed) ----------------
__device__ __nv_bfloat16 g_lnh[(size_t)MROWS * CDIM];
__device__ __nv_bfloat16 g_lnl[(size_t)MROWS * CDIM];
__device__ float         g_qkv[(size_t)MROWS * 3 * CDIM];
__device__ __nv_bfloat16 g_atth[(size_t)MROWS * CDIM];
__device__ __nv_bfloat16 g_attl[(size_t)MROWS * CDIM];
__device__ float         g_x1 [(size_t)MROWS * CDIM];
__device__ __nv_bfloat16 g_fch[(size_t)MROWS * 4 * CDIM];
__device__ __nv_bfloat16 g_fcl[(size_t)MROWS * 4 * CDIM];

#define W_QKV_N (768*2304)
#define W_PROJ_N (768*768)
#define W_FC_N (768*3072)
#define W_MP_N (3072*768)
__device__ __nv_bfloat16 g_wh[W_QKV_N + W_PROJ_N + W_FC_N + W_MP_N];
__device__ __nv_bfloat16 g_wl[W_QKV_N + W_PROJ_N + W_FC_N + W_MP_N];

// ---------------- helpers ----------------
__device__ __forceinline__ float warp_sum(float v) {
#pragma unroll
    for (int m = 16; m; m >>= 1) v += __shfl_xor_sync(0xffffffffu, v, m);
    return v;
}

__device__ __forceinline__ float gelu_tanh(float x) {
    const float c = 0.7978845608028654f;  // sqrt(2/pi)
    float x3 = x * x * x;
    return 0.5f * x * (1.0f + tanhf(c * (x + 0.044715f * x3)));
}

__device__ __forceinline__ uint32_t smem_u32(const void* p) {
    return (uint32_t)__cvta_generic_to_shared(p);
}

__device__ __forceinline__ void cp16(uint32_t dst, const void* src) {
    asm volatile("cp.async.cg.shared.global [%0], [%1], 16;\n" :: "r"(dst), "l"(src));
}
__device__ __forceinline__ void cp_commit() { asm volatile("cp.async.commit_group;\n"); }
template<int N> __device__ __forceinline__ void cp_wait() {
    asm volatile("cp.async.wait_group %0;\n" :: "n"(N));
}

__device__ __forceinline__ void ldsm_x4(uint32_t (&r)[4], uint32_t addr) {
    asm volatile("ldmatrix.sync.aligned.m8n8.x4.shared.b16 {%0,%1,%2,%3}, [%4];"
        : "=r"(r[0]), "=r"(r[1]), "=r"(r[2]), "=r"(r[3]) : "r"(addr));
}
__device__ __forceinline__ void ldsm_x4t(uint32_t (&r)[4], uint32_t addr) {
    asm volatile("ldmatrix.sync.aligned.m8n8.x4.trans.shared.b16 {%0,%1,%2,%3}, [%4];"
        : "=r"(r[0]), "=r"(r[1]), "=r"(r[2]), "=r"(r[3]) : "r"(addr));
}
__device__ __forceinline__ void mma16816(float (&d)[4], const uint32_t (&a)[4],
                                         const uint32_t (&b)[2]) {
    asm volatile(
        "mma.sync.aligned.m16n8k16.row.col.f32.bf16.bf16.f32 "
        "{%0,%1,%2,%3},{%4,%5,%6,%7},{%8,%9},{%0,%1,%2,%3};"
        : "+f"(d[0]), "+f"(d[1]), "+f"(d[2]), "+f"(d[3])
        : "r"(a[0]), "r"(a[1]), "r"(a[2]), "r"(a[3]), "r"(b[0]), "r"(b[1]));
}

__device__ __forceinline__ void split_bf16(float v, __nv_bfloat16& h, __nv_bfloat16& l) {
    h = __float2bfloat16(v);
    l = __float2bfloat16(v - __bfloat162float(h));
}

// ---------------- weight split: f32 -> bf16 hi/lo --------------------
__global__ __launch_bounds__(256) void split4_kernel(
    const float4* __restrict__ s, __nv_bfloat162* __restrict__ h,
    __nv_bfloat162* __restrict__ l, int n4)
{
    int i = blockIdx.x * 256 + threadIdx.x;
    if (i >= n4) return;
    float4 v = s[i];
    __nv_bfloat16 h0, h1, h2, h3, l0, l1, l2, l3;
    split_bf16(v.x, h0, l0); split_bf16(v.y, h1, l1);
    split_bf16(v.z, h2, l2); split_bf16(v.w, h3, l3);
    h[2 * i]     = __nv_bfloat162(h0, h1);
    h[2 * i + 1] = __nv_bfloat162(h2, h3);
    l[2 * i]     = __nv_bfloat162(l0, l1);
    l[2 * i + 1] = __nv_bfloat162(l2, l3);
}

// ---------------- LayerNorm (row = 768, ddof=1) -> bf16 hi/lo --------
__global__ __launch_bounds__(256) void ln_split_kernel(
    const float* __restrict__ x, const float* __restrict__ w,
    const float* __restrict__ b, __nv_bfloat16* __restrict__ yh,
    __nv_bfloat16* __restrict__ yl)
{
    const int row = blockIdx.x;
    const float* xr = x + (size_t)row * CDIM;
    const int t = threadIdx.x;

    float v0 = xr[t], v1 = xr[t + 256], v2 = xr[t + 512];
    float s  = v0 + v1 + v2;
    float s2 = v0 * v0 + v1 * v1 + v2 * v2;

    __shared__ float sh[2][8];
    s = warp_sum(s); s2 = warp_sum(s2);
    int wid = t >> 5, lane = t & 31;
    if (lane == 0) { sh[0][wid] = s; sh[1][wid] = s2; }
    __syncthreads();
    if (wid == 0) {
        float a = (lane < 8) ? sh[0][lane] : 0.0f;
        float c = (lane < 8) ? sh[1][lane] : 0.0f;
        a = warp_sum(a); c = warp_sum(c);
        if (lane == 0) { sh[0][0] = a; sh[1][0] = c; }
    }
    __syncthreads();
    s = sh[0][0]; s2 = sh[1][0];

    float mean = s * (1.0f / (float)CDIM);
    float var  = (s2 - (float)CDIM * mean * mean) * (1.0f / (float)(CDIM - 1));
    float rstd = rsqrtf(var + 1e-5f);

    size_t base = (size_t)row * CDIM;
#pragma unroll
    for (int j = 0; j < 3; j++) {
        int c = t + j * 256;
        float v = (j == 0 ? v0 : (j == 1 ? v1 : v2));
        float y = (v - mean) * rstd * w[c] + b[c];
        __nv_bfloat16 hh, ll;
        split_bf16(y, hh, ll);
        yh[base + c] = hh;
        yl[base + c] = ll;
    }
}

// ---------------- bf16x3 tensor-core GEMM, 128x128x32 ----------------
// EPI: 0 = +bias, 1 = gelu(+bias), 2 = +bias + residual
// STOREF: write fp32 C.  SPLIT: write bf16 hi/lo (for next GEMM input).
#define GEMM_SMEM_ELEMS (2*(2*128*40) + 2*(2*32*136))
#define GEMM_SMEM_BYTES (GEMM_SMEM_ELEMS * 2)

template<int EPI, bool STOREF, bool SPLIT>
__global__ __launch_bounds__(256, 1) void hgemm(
    int M, int N, int K,
    const __nv_bfloat16* __restrict__ Ah, const __nv_bfloat16* __restrict__ Al,
    const __nv_bfloat16* __restrict__ Bh, const __nv_bfloat16* __restrict__ Bl,
    const float* __restrict__ bias, const float* __restrict__ Res,
    float* __restrict__ C, __nv_bfloat16* __restrict__ Ch,
    __nv_bfloat16* __restrict__ Cl)
{
    extern __shared__ __nv_bfloat16 sm[];
    __nv_bfloat16* sAh = sm;                    // [2][128][40]
    __nv_bfloat16* sAl = sAh + 2 * 128 * 40;
    __nv_bfloat16* sBh = sAl + 2 * 128 * 40;    // [2][32][136]
    __nv_bfloat16* sBl = sBh + 2 * 32 * 136;
    const uint32_t uAh = smem_u32(sAh), uAl = smem_u32(sAl);
    const uint32_t uBh = smem_u32(sBh), uBl = smem_u32(sBl);

    const int tid  = threadIdx.x;
    const int warp = tid >> 5, lane = tid & 31;
    const int wr = warp >> 1, wc = warp & 1;
    const int bm = blockIdx.y * 128, bn = blockIdx.x * 128;

    float acc[2][8][4];
#pragma unroll
    for (int i = 0; i < 2; i++)
#pragma unroll
        for (int j = 0; j < 8; j++)
#pragma unroll
            for (int k = 0; k < 4; k++) acc[i][j][k] = 0.0f;

    auto load_tile = [&](int kt, int buf) {
#pragma unroll
        for (int i = 0; i < 2; i++) {
            int id = tid + i * 256;
            int r = id >> 2, c = id & 3;
            uint32_t off = (uint32_t)((buf * 128 + r) * 40 + c * 8) * 2;
            size_t g = (size_t)(bm + r) * K + kt * 32 + c * 8;
            cp16(uAh + off, Ah + g);
            cp16(uAl + off, Al + g);
        }
#pragma unroll
        for (int i = 0; i < 2; i++) {
            int id = tid + i * 256;
            int r = id >> 4, c = id & 15;
            uint32_t off = (uint32_t)((buf * 32 + r) * 136 + c * 8) * 2;
            size_t g = (size_t)(kt * 32 + r) * N + bn + c * 8;
            cp16(uBh + off, Bh + g);
            cp16(uBl + off, Bl + g);
        }
    };

    const int KT = K >> 5;
    load_tile(0, 0);
    cp_commit();

    for (int kt = 0; kt < KT; ++kt) {
        const int buf = kt & 1;
        if (kt + 1 < KT) {
            load_tile(kt + 1, buf ^ 1);
            cp_commit();
            cp_wait<1>();
        } else {
            cp_wait<0>();
        }
        __syncthreads();

#pragma unroll
        for (int ks = 0; ks < 2; ++ks) {
            uint32_t ah[2][4], al[2][4], bh[8][2], bl[8][2];
#pragma unroll
            for (int ti = 0; ti < 2; ++ti) {
                int r = wr * 32 + ti * 16 + (lane & 15);
                int col = ks * 16 + (lane >> 4) * 8;
                uint32_t off = (uint32_t)((buf * 128 + r) * 40 + col) * 2;
                ldsm_x4(ah[ti], uAh + off);
                ldsm_x4(al[ti], uAl + off);
            }
#pragma unroll
            for (int p = 0; p < 4; ++p) {
                int kr = ks * 16 + (lane & 15);
                int col = wc * 64 + p * 16 + (lane >> 4) * 8;
                uint32_t off = (uint32_t)((buf * 32 + kr) * 136 + col) * 2;
                uint32_t r4[4];
                ldsm_x4t(r4, uBh + off);
                bh[2 * p][0] = r4[0]; bh[2 * p][1] = r4[1];
                bh[2 * p + 1][0] = r4[2]; bh[2 * p + 1][1] = r4[3];
                ldsm_x4t(r4, uBl + off);
                bl[2 * p][0] = r4[0]; bl[2 * p][1] = r4[1];
                bl[2 * p + 1][0] = r4[2]; bl[2 * p + 1][1] = r4[3];
            }
#pragma unroll
            for (int ti = 0; ti < 2; ++ti)
#pragma unroll
                for (int nj = 0; nj < 8; ++nj) {
                    mma16816(acc[ti][nj], ah[ti], bh[nj]);
                    mma16816(acc[ti][nj], ah[ti], bl[nj]);
                    mma16816(acc[ti][nj], al[ti], bh[nj]);
                }
        }
        __syncthreads();
    }

    // epilogue
    const int row_base = bm + wr * 32;
    const int col_base = bn + wc * 64;
#pragma unroll
    for (int ti = 0; ti < 2; ++ti) {
        int r0 = row_base + ti * 16 + (lane >> 2);
#pragma unroll
        for (int nj = 0; nj < 8; ++nj) {
            int col = col_base + nj * 8 + (lane & 3) * 2;
            float b0 = bias[col], b1 = bias[col + 1];
            float v00 = acc[ti][nj][0] + b0, v01 = acc[ti][nj][1] + b1;
            float v10 = acc[ti][nj][2] + b0, v11 = acc[ti][nj][3] + b1;
            if (EPI == 1) {
                v00 = gelu_tanh(v00); v01 = gelu_tanh(v01);
                v10 = gelu_tanh(v10); v11 = gelu_tanh(v11);
            }
            size_t o0 = (size_t)r0 * N + col;
            size_t o1 = (size_t)(r0 + 8) * N + col;
            if (EPI == 2) {
                v00 += Res[o0]; v01 += Res[o0 + 1];
                v10 += Res[o1]; v11 += Res[o1 + 1];
            }
            if (STOREF) {
                float2 f0; f0.x = v00; f0.y = v01;
                float2 f1; f1.x = v10; f1.y = v11;
                *(float2*)(C + o0) = f0;
                *(float2*)(C + o1) = f1;
            }
            if (SPLIT) {
                __nv_bfloat16 h0, h1, h2, h3, l0, l1, l2, l3;
                split_bf16(v00, h0, l0); split_bf16(v01, h1, l1);
                split_bf16(v10, h2, l2); split_bf16(v11, h3, l3);
                *(__nv_bfloat162*)(Ch + o0) = __nv_bfloat162(h0, h1);
                *(__nv_bfloat162*)(Ch + o1) = __nv_bfloat162(h2, h3);
                *(__nv_bfloat162*)(Cl + o0) = __nv_bfloat162(l0, l1);
                *(__nv_bfloat162*)(Cl + o1) = __nv_bfloat162(l2, l3);
            }
        }
    }
}

// ---------------- Flash attention, fp32, causal, Br=Bc=64, D=64 ------
// qkv layout: [B*T, 3C]; outputs bf16 hi/lo for the proj GEMM.
#define FA_SMEM ((3 * 64 * 65 + 64 * 64) * 4)

__global__ __launch_bounds__(256) void flash_attn_kernel(
    const float* __restrict__ qkv, __nv_bfloat16* __restrict__ outh,
    __nv_bfloat16* __restrict__ outl)
{
    extern __shared__ float smf[];
    float* Qt = smf;              // [64][65]
    float* Kt = Qt + 64 * 65;     // [64][65]
    float* Pt = Kt + 64 * 65;     // [64][65]
    float* Vs = Pt + 64 * 65;     // [64][64]

    const int tid = threadIdx.x;
    const int tr = tid >> 4;
    const int tc = tid & 15;
    const int b = blockIdx.z, hh = blockIdx.y, qt = blockIdx.x;
    const int q0 = qt * 64;
    const size_t rs = 3 * CDIM;
    const float* qb = qkv + (size_t)b * TSEQ * rs + hh * HD;
    const float* kb = qb + CDIM;
    const float* vb = qb + 2 * CDIM;

#pragma unroll
    for (int it = 0; it < 4; it++) {
        int e = (tid + it * 256) * 4;
        int r = e >> 6, d = e & 63;
        float4 v = *(const float4*)(qb + (size_t)(q0 + r) * rs + d);
        Qt[(d + 0) * 65 + r] = v.x;
        Qt[(d + 1) * 65 + r] = v.y;
        Qt[(d + 2) * 65 + r] = v.z;
        Qt[(d + 3) * 65 + r] = v.w;
    }

    float o[4][4];
#pragma unroll
    for (int i = 0; i < 4; i++)
#pragma unroll
        for (int c = 0; c < 4; c++) o[i][c] = 0.0f;
    float mr[4], lr[4];
#pragma unroll
    for (int i = 0; i < 4; i++) { mr[i] = -1e30f; lr[i] = 0.0f; }

    for (int kt = 0; kt <= qt; kt++) {
        const int k0 = kt * 64;
        __syncthreads();
#pragma unroll
        for (int it = 0; it < 4; it++) {
            int e = (tid + it * 256) * 4;
            int r = e >> 6, d = e & 63;
            float4 kv = *(const float4*)(kb + (size_t)(k0 + r) * rs + d);
            Kt[(d + 0) * 65 + r] = kv.x;
            Kt[(d + 1) * 65 + r] = kv.y;
            Kt[(d + 2) * 65 + r] = kv.z;
            Kt[(d + 3) * 65 + r] = kv.w;
            float4 vv = *(const float4*)(vb + (size_t)(k0 + r) * rs + d);
            *(float4*)&Vs[r * 64 + d] = vv;
        }
        __syncthreads();

        float s[4][4];
#pragma unroll
        for (int i = 0; i < 4; i++)
#pragma unroll
            for (int j = 0; j < 4; j++) s[i][j] = 0.0f;
#pragma unroll 8
        for (int d = 0; d < 64; d++) {
            float ra[4], rb[4];
#pragma unroll
            for (int i = 0; i < 4; i++) ra[i] = Qt[d * 65 + tr * 4 + i];
#pragma unroll
            for (int j = 0; j < 4; j++) rb[j] = Kt[d * 65 + tc * 4 + j];
#pragma unroll
            for (int i = 0; i < 4; i++)
#pragma unroll
                for (int j = 0; j < 4; j++)
                    s[i][j] = fmaf(ra[i], rb[j], s[i][j]);
        }

        const float scale = 0.125f;
        const bool diag = (kt == qt);
#pragma unroll
        for (int i = 0; i < 4; i++)
#pragma unroll
            for (int j = 0; j < 4; j++) {
                s[i][j] *= scale;
                if (diag && (k0 + tc * 4 + j) > (q0 + tr * 4 + i))
                    s[i][j] = -1e30f;
            }

#pragma unroll
        for (int i = 0; i < 4; i++) {
            float tm = fmaxf(fmaxf(s[i][0], s[i][1]), fmaxf(s[i][2], s[i][3]));
#pragma unroll
            for (int m = 8; m; m >>= 1)
                tm = fmaxf(tm, __shfl_xor_sync(0xffffffffu, tm, m));
            float mn = fmaxf(mr[i], tm);
            float alpha = expf(mr[i] - mn);
            float psum = 0.0f;
#pragma unroll
            for (int j = 0; j < 4; j++) {
                s[i][j] = expf(s[i][j] - mn);
                psum += s[i][j];
            }
#pragma unroll
            for (int m = 8; m; m >>= 1)
                psum += __shfl_xor_sync(0xffffffffu, psum, m);
            lr[i] = lr[i] * alpha + psum;
            mr[i] = mn;
#pragma unroll
            for (int c = 0; c < 4; c++) o[i][c] *= alpha;
        }

#pragma unroll
        for (int i = 0; i < 4; i++)
#pragma unroll
            for (int j = 0; j < 4; j++)
                Pt[(tc * 4 + j) * 65 + tr * 4 + i] = s[i][j];
        __syncthreads();

#pragma unroll 8
        for (int j = 0; j < 64; j++) {
            float ra[4], rb[4];
#pragma unroll
            for (int i = 0; i < 4; i++) ra[i] = Pt[j * 65 + tr * 4 + i];
#pragma unroll
            for (int c = 0; c < 4; c++) rb[c] = Vs[j * 64 + tc * 4 + c];
#pragma unroll
            for (int i = 0; i < 4; i++)
#pragma unroll
                for (int c = 0; c < 4; c++)
                    o[i][c] = fmaf(ra[i], rb[c], o[i][c]);
        }
    }

#pragma unroll
    for (int i = 0; i < 4; i++) {
        float inv = 1.0f / lr[i];
        float f0 = o[i][0] * inv, f1 = o[i][1] * inv;
        float f2 = o[i][2] * inv, f3 = o[i][3] * inv;
        __nv_bfloat16 h0, h1, h2, h3, l0, l1, l2, l3;
        split_bf16(f0, h0, l0); split_bf16(f1, h1, l1);
        split_bf16(f2, h2, l2); split_bf16(f3, h3, l3);
        size_t off = (size_t)(b * TSEQ + q0 + tr * 4 + i) * CDIM + hh * HD + tc * 4;
        *(__nv_bfloat162*)(outh + off)     = __nv_bfloat162(h0, h1);
        *(__nv_bfloat162*)(outh + off + 2) = __nv_bfloat162(h2, h3);
        *(__nv_bfloat162*)(outl + off)     = __nv_bfloat162(l0, l1);
        *(__nv_bfloat162*)(outl + off + 2) = __nv_bfloat162(l2, l3);
    }
}

// ---------------- launch ----------------
extern "C" void kernel_launch(void* const* d_in, const int* in_sizes, int n_in,
                              void* d_out, int out_size)
{
    const float* x       = (const float*)d_in[0];
    const float* ln1_w   = (const float*)d_in[1];
    const float* ln1_b   = (const float*)d_in[2];
    const float* attn_w  = (const float*)d_in[3];
    const float* attn_b  = (const float*)d_in[4];
    const float* proj_w  = (const float*)d_in[5];
    const float* proj_b  = (const float*)d_in[6];
    const float* ln2_w   = (const float*)d_in[7];
    const float* ln2_b   = (const float*)d_in[8];
    const float* fc_w    = (const float*)d_in[9];
    const float* fc_b    = (const float*)d_in[10];
    const float* mproj_w = (const float*)d_in[11];
    const float* mproj_b = (const float*)d_in[12];
    float* out = (float*)d_out;

    __nv_bfloat16 *lnh, *lnl, *atth, *attl, *fch, *fcl, *wh, *wl;
    float *qkv, *x1;
    cudaGetSymbolAddress((void**)&lnh,  g_lnh);
    cudaGetSymbolAddress((void**)&lnl,  g_lnl);
    cudaGetSymbolAddress((void**)&qkv,  g_qkv);
    cudaGetSymbolAddress((void**)&atth, g_atth);
    cudaGetSymbolAddress((void**)&attl, g_attl);
    cudaGetSymbolAddress((void**)&x1,   g_x1);
    cudaGetSymbolAddress((void**)&fch,  g_fch);
    cudaGetSymbolAddress((void**)&fcl,  g_fcl);
    cudaGetSymbolAddress((void**)&wh,   g_wh);
    cudaGetSymbolAddress((void**)&wl,   g_wl);

    __nv_bfloat16 *wqkvh = wh,                 *wqkvl = wl;
    __nv_bfloat16 *wprojh = wh + W_QKV_N,      *wprojl = wl + W_QKV_N;
    __nv_bfloat16 *wfch = wprojh + W_PROJ_N,   *wfcl = wprojl + W_PROJ_N;
    __nv_bfloat16 *wmph = wfch + W_FC_N,       *wmpl = wfcl + W_FC_N;

    cudaFuncSetAttribute(flash_attn_kernel,
                         cudaFuncAttributeMaxDynamicSharedMemorySize, FA_SMEM);
    cudaFuncSetAttribute((const void*)hgemm<0, true, false>,
                         cudaFuncAttributeMaxDynamicSharedMemorySize, GEMM_SMEM_BYTES);
    cudaFuncSetAttribute((const void*)hgemm<2, true, false>,
                         cudaFuncAttributeMaxDynamicSharedMemorySize, GEMM_SMEM_BYTES);
    cudaFuncSetAttribute((const void*)hgemm<1, false, true>,
                         cudaFuncAttributeMaxDynamicSharedMemorySize, GEMM_SMEM_BYTES);

    // 0) split weights to bf16 hi/lo
    split4_kernel<<<(W_QKV_N / 4 + 255) / 256, 256>>>(
        (const float4*)attn_w, (__nv_bfloat162*)wqkvh, (__nv_bfloat162*)wqkvl, W_QKV_N / 4);
    split4_kernel<<<(W_PROJ_N / 4 + 255) / 256, 256>>>(
        (const float4*)proj_w, (__nv_bfloat162*)wprojh, (__nv_bfloat162*)wprojl, W_PROJ_N / 4);
    split4_kernel<<<(W_FC_N / 4 + 255) / 256, 256>>>(
        (const float4*)fc_w, (__nv_bfloat162*)wfch, (__nv_bfloat162*)wfcl, W_FC_N / 4);
    split4_kernel<<<(W_MP_N / 4 + 255) / 256, 256>>>(
        (const float4*)mproj_w, (__nv_bfloat162*)wmph, (__nv_bfloat162*)wmpl, W_MP_N / 4);

    // 1) ln1 -> bf16 hi/lo
    ln_split_kernel<<<MROWS, 256>>>(x, ln1_w, ln1_b, lnh, lnl);
    // 2) qkv = ln1 @ W_attn + b   [8192, 2304] fp32
    hgemm<0, true, false><<<dim3(2304 / 128, MROWS / 128), 256, GEMM_SMEM_BYTES>>>(
        MROWS, 2304, CDIM, lnh, lnl, wqkvh, wqkvl, attn_b, nullptr,
        qkv, nullptr, nullptr);
    // 3) attention -> bf16 hi/lo
    flash_attn_kernel<<<dim3(TSEQ / 64, NHEAD, NBATCH), 256, FA_SMEM>>>(qkv, atth, attl);
    // 4) x1 = x + att @ W_proj + b   (fp32)
    hgemm<2, true, false><<<dim3(CDIM / 128, MROWS / 128), 256, GEMM_SMEM_BYTES>>>(
        MROWS, CDIM, CDIM, atth, attl, wprojh, wprojl, proj_b, x,
        x1, nullptr, nullptr);
    // 5) ln2 -> bf16 hi/lo
    ln_split_kernel<<<MROWS, 256>>>(x1, ln2_w, ln2_b, lnh, lnl);
    // 6) fc = gelu(ln2 @ W_fc + b)   [8192, 3072] -> bf16 hi/lo only
    hgemm<1, false, true><<<dim3(3072 / 128, MROWS / 128), 256, GEMM_SMEM_BYTES>>>(
        MROWS, 3072, CDIM, lnh, lnl, wfch, wfcl, fc_b, nullptr,
        nullptr, fch, fcl);
    // 7) out = x1 + fc @ W_mproj + b   (fp32)
    hgemm<2, true, false><<<dim3(CDIM / 128, MROWS / 128), 256, GEMM_SMEM_BYTES>>>(
        MROWS, CDIM, 4 * CDIM, fch, fcl, wmph, wmpl, mproj_b, x1,
        out, nullptr, nullptr);
}

// round 4
// speedup vs baseline: 2.6118x; 1.4204x over previous
#include <cuda_runtime.h>
#include <cuda_bf16.h>
#include <math.h>
#include <stdint.h>

#define MROWS 8192           // B*T = 4*2048
#define CDIM  768
#define TSEQ  2048
#define NBATCH 4
#define NHEAD 12
#define HD    64

// ---------------- scratch (no allocations allowed) ----------------
__device__ __nv_bfloat16 g_lnh[(size_t)MROWS * CDIM];
__device__ __nv_bfloat16 g_lnl[(size_t)MROWS * CDIM];
__device__ __nv_bfloat16 g_qkvh[(size_t)MROWS * 3 * CDIM];
__device__ __nv_bfloat16 g_qkvl[(size_t)MROWS * 3 * CDIM];
__device__ __nv_bfloat16 g_atth[(size_t)MROWS * CDIM];
__device__ __nv_bfloat16 g_attl[(size_t)MROWS * CDIM];
__device__ float         g_x1 [(size_t)MROWS * CDIM];
__device__ __nv_bfloat16 g_fch[(size_t)MROWS * 4 * CDIM];
__device__ __nv_bfloat16 g_fcl[(size_t)MROWS * 4 * CDIM];

#define W_QKV_N (768*2304)
#define W_PROJ_N (768*768)
#define W_FC_N (768*3072)
#define W_MP_N (3072*768)
__device__ __nv_bfloat16 g_wh[W_QKV_N + W_PROJ_N + W_FC_N + W_MP_N];
__device__ __nv_bfloat16 g_wl[W_QKV_N + W_PROJ_N + W_FC_N + W_MP_N];

// ---------------- helpers ----------------
__device__ __forceinline__ float warp_sum(float v) {
#pragma unroll
    for (int m = 16; m; m >>= 1) v += __shfl_xor_sync(0xffffffffu, v, m);
    return v;
}

__device__ __forceinline__ float gelu_tanh(float x) {
    const float c = 0.7978845608028654f;  // sqrt(2/pi)
    float x3 = x * x * x;
    return 0.5f * x * (1.0f + tanhf(c * (x + 0.044715f * x3)));
}

__device__ __forceinline__ uint32_t smem_u32(const void* p) {
    return (uint32_t)__cvta_generic_to_shared(p);
}

__device__ __forceinline__ void cp16(uint32_t dst, const void* src) {
    asm volatile("cp.async.cg.shared.global [%0], [%1], 16;\n" :: "r"(dst), "l"(src));
}
__device__ __forceinline__ void cp_commit() { asm volatile("cp.async.commit_group;\n"); }
template<int N> __device__ __forceinline__ void cp_wait() {
    asm volatile("cp.async.wait_group %0;\n" :: "n"(N));
}

__device__ __forceinline__ void ldsm_x4(uint32_t (&r)[4], uint32_t addr) {
    asm volatile("ldmatrix.sync.aligned.m8n8.x4.shared.b16 {%0,%1,%2,%3}, [%4];"
        : "=r"(r[0]), "=r"(r[1]), "=r"(r[2]), "=r"(r[3]) : "r"(addr));
}
__device__ __forceinline__ void ldsm_x4t(uint32_t (&r)[4], uint32_t addr) {
    asm volatile("ldmatrix.sync.aligned.m8n8.x4.trans.shared.b16 {%0,%1,%2,%3}, [%4];"
        : "=r"(r[0]), "=r"(r[1]), "=r"(r[2]), "=r"(r[3]) : "r"(addr));
}
__device__ __forceinline__ void mma16816(float (&d)[4], const uint32_t (&a)[4],
                                         const uint32_t (&b)[2]) {
    asm volatile(
        "mma.sync.aligned.m16n8k16.row.col.f32.bf16.bf16.f32 "
        "{%0,%1,%2,%3},{%4,%5,%6,%7},{%8,%9},{%0,%1,%2,%3};"
        : "+f"(d[0]), "+f"(d[1]), "+f"(d[2]), "+f"(d[3])
        : "r"(a[0]), "r"(a[1]), "r"(a[2]), "r"(a[3]), "r"(b[0]), "r"(b[1]));
}

__device__ __forceinline__ void split_bf16(float v, __nv_bfloat16& h, __nv_bfloat16& l) {
    h = __float2bfloat16(v);
    l = __float2bfloat16(v - __bfloat162float(h));
}

__device__ __forceinline__ void packsplit(float x0, float x1, uint32_t& h, uint32_t& l) {
    __nv_bfloat16 h0, h1, l0, l1;
    split_bf16(x0, h0, l0);
    split_bf16(x1, h1, l1);
    __nv_bfloat162 hv(h0, h1), lv(l0, l1);
    h = *(uint32_t*)&hv;
    l = *(uint32_t*)&lv;
}

// ---------------- weight split: f32 -> bf16 hi/lo --------------------
__global__ __launch_bounds__(256) void split4_kernel(
    const float4* __restrict__ s, __nv_bfloat162* __restrict__ h,
    __nv_bfloat162* __restrict__ l, int n4)
{
    int i = blockIdx.x * 256 + threadIdx.x;
    if (i >= n4) return;
    float4 v = s[i];
    __nv_bfloat16 h0, h1, h2, h3, l0, l1, l2, l3;
    split_bf16(v.x, h0, l0); split_bf16(v.y, h1, l1);
    split_bf16(v.z, h2, l2); split_bf16(v.w, h3, l3);
    h[2 * i]     = __nv_bfloat162(h0, h1);
    h[2 * i + 1] = __nv_bfloat162(h2, h3);
    l[2 * i]     = __nv_bfloat162(l0, l1);
    l[2 * i + 1] = __nv_bfloat162(l2, l3);
}

// ---------------- LayerNorm (row = 768, ddof=1) -> bf16 hi/lo --------
__global__ __launch_bounds__(256) void ln_split_kernel(
    const float* __restrict__ x, const float* __restrict__ w,
    const float* __restrict__ b, __nv_bfloat16* __restrict__ yh,
    __nv_bfloat16* __restrict__ yl)
{
    const int row = blockIdx.x;
    const float* xr = x + (size_t)row * CDIM;
    const int t = threadIdx.x;

    float v0 = xr[t], v1 = xr[t + 256], v2 = xr[t + 512];
    float s  = v0 + v1 + v2;
    float s2 = v0 * v0 + v1 * v1 + v2 * v2;

    __shared__ float sh[2][8];
    s = warp_sum(s); s2 = warp_sum(s2);
    int wid = t >> 5, lane = t & 31;
    if (lane == 0) { sh[0][wid] = s; sh[1][wid] = s2; }
    __syncthreads();
    if (wid == 0) {
        float a = (lane < 8) ? sh[0][lane] : 0.0f;
        float c = (lane < 8) ? sh[1][lane] : 0.0f;
        a = warp_sum(a); c = warp_sum(c);
        if (lane == 0) { sh[0][0] = a; sh[1][0] = c; }
    }
    __syncthreads();
    s = sh[0][0]; s2 = sh[1][0];

    float mean = s * (1.0f / (float)CDIM);
    float var  = (s2 - (float)CDIM * mean * mean) * (1.0f / (float)(CDIM - 1));
    float rstd = rsqrtf(var + 1e-5f);

    size_t base = (size_t)row * CDIM;
#pragma unroll
    for (int j = 0; j < 3; j++) {
        int c = t + j * 256;
        float v = (j == 0 ? v0 : (j == 1 ? v1 : v2));
        float y = (v - mean) * rstd * w[c] + b[c];
        __nv_bfloat16 hh, ll;
        split_bf16(y, hh, ll);
        yh[base + c] = hh;
        yl[base + c] = ll;
    }
}

// ---------------- bf16x3 tensor-core GEMM, 128x128x32 ----------------
#define GEMM_SMEM_ELEMS (2*(2*128*40) + 2*(2*32*136))
#define GEMM_SMEM_BYTES (GEMM_SMEM_ELEMS * 2)

template<int EPI, bool STOREF, bool SPLIT>
__global__ __launch_bounds__(256, 1) void hgemm(
    int M, int N, int K,
    const __nv_bfloat16* __restrict__ Ah, const __nv_bfloat16* __restrict__ Al,
    const __nv_bfloat16* __restrict__ Bh, const __nv_bfloat16* __restrict__ Bl,
    const float* __restrict__ bias, const float* __restrict__ Res,
    float* __restrict__ C, __nv_bfloat16* __restrict__ Ch,
    __nv_bfloat16* __restrict__ Cl)
{
    extern __shared__ __nv_bfloat16 sm[];
    __nv_bfloat16* sAh = sm;                    // [2][128][40]
    __nv_bfloat16* sAl = sAh + 2 * 128 * 40;
    __nv_bfloat16* sBh = sAl + 2 * 128 * 40;    // [2][32][136]
    __nv_bfloat16* sBl = sBh + 2 * 32 * 136;
    const uint32_t uAh = smem_u32(sAh), uAl = smem_u32(sAl);
    const uint32_t uBh = smem_u32(sBh), uBl = smem_u32(sBl);

    const int tid  = threadIdx.x;
    const int warp = tid >> 5, lane = tid & 31;
    const int wr = warp >> 1, wc = warp & 1;
    const int bm = blockIdx.y * 128, bn = blockIdx.x * 128;

    float acc[2][8][4];
#pragma unroll
    for (int i = 0; i < 2; i++)
#pragma unroll
        for (int j = 0; j < 8; j++)
#pragma unroll
            for (int k = 0; k < 4; k++) acc[i][j][k] = 0.0f;

    auto load_tile = [&](int kt, int buf) {
#pragma unroll
        for (int i = 0; i < 2; i++) {
            int id = tid + i * 256;
            int r = id >> 2, c = id & 3;
            uint32_t off = (uint32_t)((buf * 128 + r) * 40 + c * 8) * 2;
            size_t g = (size_t)(bm + r) * K + kt * 32 + c * 8;
            cp16(uAh + off, Ah + g);
            cp16(uAl + off, Al + g);
        }
#pragma unroll
        for (int i = 0; i < 2; i++) {
            int id = tid + i * 256;
            int r = id >> 4, c = id & 15;
            uint32_t off = (uint32_t)((buf * 32 + r) * 136 + c * 8) * 2;
            size_t g = (size_t)(kt * 32 + r) * N + bn + c * 8;
            cp16(uBh + off, Bh + g);
            cp16(uBl + off, Bl + g);
        }
    };

    const int KT = K >> 5;
    load_tile(0, 0);
    cp_commit();

    for (int kt = 0; kt < KT; ++kt) {
        const int buf = kt & 1;
        if (kt + 1 < KT) {
            load_tile(kt + 1, buf ^ 1);
            cp_commit();
            cp_wait<1>();
        } else {
            cp_wait<0>();
        }
        __syncthreads();

#pragma unroll
        for (int ks = 0; ks < 2; ++ks) {
            uint32_t ah[2][4], al[2][4], bh[8][2], bl[8][2];
#pragma unroll
            for (int ti = 0; ti < 2; ++ti) {
                int r = wr * 32 + ti * 16 + (lane & 15);
                int col = ks * 16 + (lane >> 4) * 8;
                uint32_t off = (uint32_t)((buf * 128 + r) * 40 + col) * 2;
                ldsm_x4(ah[ti], uAh + off);
                ldsm_x4(al[ti], uAl + off);
            }
#pragma unroll
            for (int p = 0; p < 4; ++p) {
                int kr = ks * 16 + (lane & 15);
                int col = wc * 64 + p * 16 + (lane >> 4) * 8;
                uint32_t off = (uint32_t)((buf * 32 + kr) * 136 + col) * 2;
                uint32_t r4[4];
                ldsm_x4t(r4, uBh + off);
                bh[2 * p][0] = r4[0]; bh[2 * p][1] = r4[1];
                bh[2 * p + 1][0] = r4[2]; bh[2 * p + 1][1] = r4[3];
                ldsm_x4t(r4, uBl + off);
                bl[2 * p][0] = r4[0]; bl[2 * p][1] = r4[1];
                bl[2 * p + 1][0] = r4[2]; bl[2 * p + 1][1] = r4[3];
            }
#pragma unroll
            for (int ti = 0; ti < 2; ++ti)
#pragma unroll
                for (int nj = 0; nj < 8; ++nj) {
                    mma16816(acc[ti][nj], ah[ti], bh[nj]);
                    mma16816(acc[ti][nj], ah[ti], bl[nj]);
                    mma16816(acc[ti][nj], al[ti], bh[nj]);
                }
        }
        __syncthreads();
    }

    const int row_base = bm + wr * 32;
    const int col_base = bn + wc * 64;
#pragma unroll
    for (int ti = 0; ti < 2; ++ti) {
        int r0 = row_base + ti * 16 + (lane >> 2);
#pragma unroll
        for (int nj = 0; nj < 8; ++nj) {
            int col = col_base + nj * 8 + (lane & 3) * 2;
            float b0 = bias[col], b1 = bias[col + 1];
            float v00 = acc[ti][nj][0] + b0, v01 = acc[ti][nj][1] + b1;
            float v10 = acc[ti][nj][2] + b0, v11 = acc[ti][nj][3] + b1;
            if (EPI == 1) {
                v00 = gelu_tanh(v00); v01 = gelu_tanh(v01);
                v10 = gelu_tanh(v10); v11 = gelu_tanh(v11);
            }
            size_t o0 = (size_t)r0 * N + col;
            size_t o1 = (size_t)(r0 + 8) * N + col;
            if (EPI == 2) {
                v00 += Res[o0]; v01 += Res[o0 + 1];
                v10 += Res[o1]; v11 += Res[o1 + 1];
            }
            if (STOREF) {
                float2 f0; f0.x = v00; f0.y = v01;
                float2 f1; f1.x = v10; f1.y = v11;
                *(float2*)(C + o0) = f0;
                *(float2*)(C + o1) = f1;
            }
            if (SPLIT) {
                uint32_t h0, l0, h1, l1;
                packsplit(v00, v01, h0, l0);
                packsplit(v10, v11, h1, l1);
                *(uint32_t*)(Ch + o0) = h0;
                *(uint32_t*)(Ch + o1) = h1;
                *(uint32_t*)(Cl + o0) = l0;
                *(uint32_t*)(Cl + o1) = l1;
            }
        }
    }
}

// ---------------- Flash attention, bf16x3 tensor cores ----------------
// Br=128 (8 warps), Bc=64. qkv split hi/lo, [row][3C] layout.
#define FAP 72
#define FA_Q_ELEMS (128 * FAP)
#define FA_KV_ELEMS (64 * FAP)
#define FA2_SMEM ((2 * FA_Q_ELEMS + 8 * FA_KV_ELEMS) * 2)

__global__ __launch_bounds__(256) void flash_attn_tc(
    const __nv_bfloat16* __restrict__ qh_g, const __nv_bfloat16* __restrict__ ql_g,
    __nv_bfloat16* __restrict__ outh, __nv_bfloat16* __restrict__ outl)
{
    extern __shared__ __nv_bfloat16 sb[];
    __nv_bfloat16* sQh = sb;                      // [128][72]
    __nv_bfloat16* sQl = sQh + FA_Q_ELEMS;
    __nv_bfloat16* sKV = sQl + FA_Q_ELEMS;        // [2][Kh,Kl,Vh,Vl][64][72]

    const int tid = threadIdx.x, lane = tid & 31, w = tid >> 5;
    const int b = blockIdx.z, h = blockIdx.y, qtb = blockIdx.x;
    const int q0 = qtb * 128;
    const size_t rs = 3 * CDIM;
    const __nv_bfloat16* baseh = qh_g + (size_t)b * TSEQ * rs + h * HD;
    const __nv_bfloat16* basel = ql_g + (size_t)b * TSEQ * rs + h * HD;

    // load Q tile (128 rows x 64 dims, hi+lo)
#pragma unroll
    for (int i = 0; i < 4; i++) {
        int id = tid + i * 256;
        int r = id >> 3, c8 = id & 7;
        size_t g = (size_t)(q0 + r) * rs + c8 * 8;
        cp16(smem_u32(sQh + r * FAP + c8 * 8), baseh + g);
        cp16(smem_u32(sQl + r * FAP + c8 * 8), basel + g);
    }

    auto loadKV = [&](int kt, int buf) {
        const int k0 = kt * 64;
        __nv_bfloat16* d = sKV + buf * 4 * FA_KV_ELEMS;
        const __nv_bfloat16* srcs[4] = { baseh + CDIM, basel + CDIM,
                                         baseh + 2 * CDIM, basel + 2 * CDIM };
#pragma unroll
        for (int a = 0; a < 4; a++) {
#pragma unroll
            for (int i = 0; i < 2; i++) {
                int id = tid + i * 256;
                int r = id >> 3, c8 = id & 7;
                cp16(smem_u32(d + a * FA_KV_ELEMS + r * FAP + c8 * 8),
                     srcs[a] + (size_t)(k0 + r) * rs + c8 * 8);
            }
        }
    };

    loadKV(0, 0);
    cp_commit();

    float o[8][4];
#pragma unroll
    for (int nt = 0; nt < 8; nt++)
#pragma unroll
        for (int e = 0; e < 4; e++) o[nt][e] = 0.0f;
    float m[2] = {-1e30f, -1e30f}, l[2] = {0.0f, 0.0f};
    uint32_t qh[4][4], ql[4][4];

    const int ktmax = 2 * qtb + 1;
    const int rmin = q0 + w * 16;        // first row this warp owns
    const int rmax = rmin + 15;          // last row this warp owns

    for (int kt = 0; kt <= ktmax; kt++) {
        const int buf = kt & 1;
        if (kt < ktmax) {
            loadKV(kt + 1, buf ^ 1);
            cp_commit();
            cp_wait<1>();
        } else {
            cp_wait<0>();
        }
        __syncthreads();

        if (kt == 0) {
#pragma unroll
            for (int ks = 0; ks < 4; ks++) {
                uint32_t off = (uint32_t)((w * 16 + (lane & 15)) * FAP
                                          + ks * 16 + (lane >> 4) * 8) * 2;
                ldsm_x4(qh[ks], smem_u32(sQh) + off);
                ldsm_x4(ql[ks], smem_u32(sQl) + off);
            }
        }

        const int k0 = kt * 64;
        if (k0 <= rmax) {
            __nv_bfloat16* Kh = sKV + buf * 4 * FA_KV_ELEMS;
            __nv_bfloat16* Kl = Kh + FA_KV_ELEMS;
            __nv_bfloat16* Vh = Kh + 2 * FA_KV_ELEMS;
            __nv_bfloat16* Vl = Kh + 3 * FA_KV_ELEMS;

            float s[8][4];
#pragma unroll
            for (int nt = 0; nt < 8; nt++)
#pragma unroll
                for (int e = 0; e < 4; e++) s[nt][e] = 0.0f;

            // S = Q K^T  (bf16x3)
#pragma unroll
            for (int ks = 0; ks < 4; ks++) {
#pragma unroll
                for (int p = 0; p < 4; p++) {
                    uint32_t roff = (uint32_t)((p * 16 + ((lane >> 4) << 3) + (lane & 7)) * FAP
                                               + ks * 16 + (((lane >> 3) & 1) << 3)) * 2;
                    uint32_t bh4[4], bl4[4];
                    ldsm_x4(bh4, smem_u32(Kh) + roff);
                    ldsm_x4(bl4, smem_u32(Kl) + roff);
                    uint32_t b0h[2] = {bh4[0], bh4[1]}, b1h[2] = {bh4[2], bh4[3]};
                    uint32_t b0l[2] = {bl4[0], bl4[1]}, b1l[2] = {bl4[2], bl4[3]};
                    mma16816(s[2 * p],     qh[ks], b0h);
                    mma16816(s[2 * p],     qh[ks], b0l);
                    mma16816(s[2 * p],     ql[ks], b0h);
                    mma16816(s[2 * p + 1], qh[ks], b1h);
                    mma16816(s[2 * p + 1], qh[ks], b1l);
                    mma16816(s[2 * p + 1], ql[ks], b1h);
                }
            }

            // scale into log2 domain
            const float SC = 0.18033688011112042f;  // 0.125 * log2(e)
#pragma unroll
            for (int nt = 0; nt < 8; nt++)
#pragma unroll
                for (int e = 0; e < 4; e++) s[nt][e] *= SC;

            // causal mask: needed whenever this tile's last column can exceed
            // the warp's FIRST row (fix: was rmax, which skipped diagonal tiles
            // ending exactly at rmax for warps 3 and 7)
            if (k0 + 63 > rmin) {
#pragma unroll
                for (int nt = 0; nt < 8; nt++)
#pragma unroll
                    for (int e = 0; e < 4; e++) {
                        int col = k0 + nt * 8 + 2 * (lane & 3) + (e & 1);
                        int row = rmin + (lane >> 2) + (e >> 1) * 8;
                        if (col > row) s[nt][e] = -1e30f;
                    }
            }

            // online softmax (quad lanes share a row)
#pragma unroll
            for (int half = 0; half < 2; half++) {
                float tm = -1e30f;
#pragma unroll
                for (int nt = 0; nt < 8; nt++)
                    tm = fmaxf(tm, fmaxf(s[nt][2 * half], s[nt][2 * half + 1]));
                tm = fmaxf(tm, __shfl_xor_sync(0xffffffffu, tm, 1));
                tm = fmaxf(tm, __shfl_xor_sync(0xffffffffu, tm, 2));
                float mn = fmaxf(m[half], tm);
                float alpha = exp2f(m[half] - mn);
                m[half] = mn;
                float ps = 0.0f;
#pragma unroll
                for (int nt = 0; nt < 8; nt++) {
                    s[nt][2 * half]     = exp2f(s[nt][2 * half] - mn);
                    s[nt][2 * half + 1] = exp2f(s[nt][2 * half + 1] - mn);
                    ps += s[nt][2 * half] + s[nt][2 * half + 1];
                }
                l[half] = l[half] * alpha + ps;
#pragma unroll
                for (int nt = 0; nt < 8; nt++) {
                    o[nt][2 * half]     *= alpha;
                    o[nt][2 * half + 1] *= alpha;
                }
            }

            // O += P V   (P split hi/lo in regs; V bf16 hi/lo)
#pragma unroll
            for (int ks = 0; ks < 4; ks++) {
                uint32_t pah[4], pal[4];
                packsplit(s[2 * ks][0],     s[2 * ks][1],     pah[0], pal[0]);
                packsplit(s[2 * ks][2],     s[2 * ks][3],     pah[1], pal[1]);
                packsplit(s[2 * ks + 1][0], s[2 * ks + 1][1], pah[2], pal[2]);
                packsplit(s[2 * ks + 1][2], s[2 * ks + 1][3], pah[3], pal[3]);
#pragma unroll
                for (int p = 0; p < 4; p++) {
                    uint32_t roff = (uint32_t)((ks * 16 + (lane & 15)) * FAP
                                               + p * 16 + (lane >> 4) * 8) * 2;
                    uint32_t vh4[4], vl4[4];
                    ldsm_x4t(vh4, smem_u32(Vh) + roff);
                    ldsm_x4t(vl4, smem_u32(Vl) + roff);
                    uint32_t b0h[2] = {vh4[0], vh4[1]}, b1h[2] = {vh4[2], vh4[3]};
                    uint32_t b0l[2] = {vl4[0], vl4[1]}, b1l[2] = {vl4[2], vl4[3]};
                    mma16816(o[2 * p],     pah, b0h);
                    mma16816(o[2 * p],     pah, b0l);
                    mma16816(o[2 * p],     pal, b0h);
                    mma16816(o[2 * p + 1], pah, b1h);
                    mma16816(o[2 * p + 1], pah, b1l);
                    mma16816(o[2 * p + 1], pal, b1h);
                }
            }
        }
        __syncthreads();
    }

    // final normalize + split-write
    float linv[2];
#pragma unroll
    for (int half = 0; half < 2; half++) {
        float lv = l[half];
        lv += __shfl_xor_sync(0xffffffffu, lv, 1);
        lv += __shfl_xor_sync(0xffffffffu, lv, 2);
        linv[half] = 1.0f / lv;
    }
#pragma unroll
    for (int nt = 0; nt < 8; nt++) {
#pragma unroll
        for (int half = 0; half < 2; half++) {
            int rowg = q0 + w * 16 + (lane >> 2) + half * 8;
            int colg = h * HD + nt * 8 + 2 * (lane & 3);
            float f0 = o[nt][2 * half]     * linv[half];
            float f1 = o[nt][2 * half + 1] * linv[half];
            uint32_t hv, lv;
            packsplit(f0, f1, hv, lv);
            size_t off = (size_t)(b * TSEQ + rowg) * CDIM + colg;
            *(uint32_t*)(outh + off) = hv;
            *(uint32_t*)(outl + off) = lv;
        }
    }
}

// ---------------- launch ----------------
extern "C" void kernel_launch(void* const* d_in, const int* in_sizes, int n_in,
                              void* d_out, int out_size)
{
    const float* x       = (const float*)d_in[0];
    const float* ln1_w   = (const float*)d_in[1];
    const float* ln1_b   = (const float*)d_in[2];
    const float* attn_w  = (const float*)d_in[3];
    const float* attn_b  = (const float*)d_in[4];
    const float* proj_w  = (const float*)d_in[5];
    const float* proj_b  = (const float*)d_in[6];
    const float* ln2_w   = (const float*)d_in[7];
    const float* ln2_b   = (const float*)d_in[8];
    const float* fc_w    = (const float*)d_in[9];
    const float* fc_b    = (const float*)d_in[10];
    const float* mproj_w = (const float*)d_in[11];
    const float* mproj_b = (const float*)d_in[12];
    float* out = (float*)d_out;

    __nv_bfloat16 *lnh, *lnl, *qkvh, *qkvl, *atth, *attl, *fch, *fcl, *wh, *wl;
    float *x1;
    cudaGetSymbolAddress((void**)&lnh,  g_lnh);
    cudaGetSymbolAddress((void**)&lnl,  g_lnl);
    cudaGetSymbolAddress((void**)&qkvh, g_qkvh);
    cudaGetSymbolAddress((void**)&qkvl, g_qkvl);
    cudaGetSymbolAddress((void**)&atth, g_atth);
    cudaGetSymbolAddress((void**)&attl, g_attl);
    cudaGetSymbolAddress((void**)&x1,   g_x1);
    cudaGetSymbolAddress((void**)&fch,  g_fch);
    cudaGetSymbolAddress((void**)&fcl,  g_fcl);
    cudaGetSymbolAddress((void**)&wh,   g_wh);
    cudaGetSymbolAddress((void**)&wl,   g_wl);

    __nv_bfloat16 *wqkvh = wh,                 *wqkvl = wl;
    __nv_bfloat16 *wprojh = wh + W_QKV_N,      *wprojl = wl + W_QKV_N;
    __nv_bfloat16 *wfch = wprojh + W_PROJ_N,   *wfcl = wprojl + W_PROJ_N;
    __nv_bfloat16 *wmph = wfch + W_FC_N,       *wmpl = wfcl + W_FC_N;

    cudaFuncSetAttribute(flash_attn_tc,
                         cudaFuncAttributeMaxDynamicSharedMemorySize, FA2_SMEM);
    cudaFuncSetAttribute((const void*)hgemm<0, false, true>,
                         cudaFuncAttributeMaxDynamicSharedMemorySize, GEMM_SMEM_BYTES);
    cudaFuncSetAttribute((const void*)hgemm<2, true, false>,
                         cudaFuncAttributeMaxDynamicSharedMemorySize, GEMM_SMEM_BYTES);
    cudaFuncSetAttribute((const void*)hgemm<1, false, true>,
                         cudaFuncAttributeMaxDynamicSharedMemorySize, GEMM_SMEM_BYTES);

    // 0) split weights to bf16 hi/lo
    split4_kernel<<<(W_QKV_N / 4 + 255) / 256, 256>>>(
        (const float4*)attn_w, (__nv_bfloat162*)wqkvh, (__nv_bfloat162*)wqkvl, W_QKV_N / 4);
    split4_kernel<<<(W_PROJ_N / 4 + 255) / 256, 256>>>(
        (const float4*)proj_w, (__nv_bfloat162*)wprojh, (__nv_bfloat162*)wprojl, W_PROJ_N / 4);
    split4_kernel<<<(W_FC_N / 4 + 255) / 256, 256>>>(
        (const float4*)fc_w, (__nv_bfloat162*)wfch, (__nv_bfloat162*)wfcl, W_FC_N / 4);
    split4_kernel<<<(W_MP_N / 4 + 255) / 256, 256>>>(
        (const float4*)mproj_w, (__nv_bfloat162*)wmph, (__nv_bfloat162*)wmpl, W_MP_N / 4);

    // 1) ln1 -> bf16 hi/lo
    ln_split_kernel<<<MROWS, 256>>>(x, ln1_w, ln1_b, lnh, lnl);
    // 2) qkv = ln1 @ W_attn + b   [8192, 2304] -> split bf16
    hgemm<0, false, true><<<dim3(2304 / 128, MROWS / 128), 256, GEMM_SMEM_BYTES>>>(
        MROWS, 2304, CDIM, lnh, lnl, wqkvh, wqkvl, attn_b, nullptr,
        nullptr, qkvh, qkvl);
    // 3) attention (tensor cores) -> bf16 hi/lo
    flash_attn_tc<<<dim3(TSEQ / 128, NHEAD, NBATCH), 256, FA2_SMEM>>>(
        qkvh, qkvl, atth, attl);
    // 4) x1 = x + att @ W_proj + b   (fp32)
    hgemm<2, true, false><<<dim3(CDIM / 128, MROWS / 128), 256, GEMM_SMEM_BYTES>>>(
        MROWS, CDIM, CDIM, atth, attl, wprojh, wprojl, proj_b, x,
        x1, nullptr, nullptr);
    // 5) ln2 -> bf16 hi/lo
    ln_split_kernel<<<MROWS, 256>>>(x1, ln2_w, ln2_b, lnh, lnl);
    // 6) fc = gelu(ln2 @ W_fc + b)   [8192, 3072] -> bf16 hi/lo
    hgemm<1, false, true><<<dim3(3072 / 128, MROWS / 128), 256, GEMM_SMEM_BYTES>>>(
        MROWS, 3072, CDIM, lnh, lnl, wfch, wfcl, fc_b, nullptr,
        nullptr, fch, fcl);
    // 7) out = x1 + fc @ W_mproj + b   (fp32)
    hgemm<2, true, false><<<dim3(CDIM / 128, MROWS / 128), 256, GEMM_SMEM_BYTES>>>(
        MROWS, CDIM, 4 * CDIM, fch, fcl, wmph, wmpl, mproj_b, x1,
        out, nullptr, nullptr);
}